// round 2
// baseline (speedup 1.0000x reference)
#include <cuda_runtime.h>
#include <math.h>

typedef unsigned long long ull;

#define Bn 2048
#define Sn 50
#define En 300
#define Tn 8
#define Cn 4
#define Un 300
#define Ln 1000
#define NPAIR 44850
#define KPAD  44864      // NPAIR padded to multiple of 32
#define NOP   320        // fc7 output cols padded (300 -> 320)
#define EPSf  1e-5f
#define PADVAL (-4294967295.0f)
#define KSPLIT 8
#define NCHUNK (KPAD/32) // 1402

// ------------------------- scratch (device globals) -------------------------
__device__ float d_W7gT[(size_t)KPAD * NOP];   // 57.4 MB: fc7_w^T * g, zero-padded
__device__ unsigned int d_pairs[KPAD];
__device__ float d_g[NPAIR];
__device__ float d_Aq [2][Bn*Sn];
__device__ float d_Asm[2][Bn*Sn];
__device__ float d_Asq[2][Bn*Sn];
__device__ float d_sgn[Bn*Sn];
__device__ float d_m [2][Sn];
__device__ float d_is[2][Sn];
__device__ float d_Q [2];
__device__ float d_h   [(size_t)Bn*600];
__device__ float d_h5  [(size_t)Bn*En];
__device__ float d_h6p [(size_t)Bn*En];
__device__ float d_h7p [(size_t)Bn*En];
__device__ float d_hcat[(size_t)Bn*600];
__device__ float d_out8[(size_t)Bn*Un];
__device__ float d_cm[1024], d_cis[1024];

// ------------------------- f32x2 packed helpers -----------------------------
__device__ __forceinline__ ull pack2(float x, float y) {
    ull r; asm("mov.b64 %0, {%1,%2};" : "=l"(r) : "f"(x), "f"(y)); return r;
}
__device__ __forceinline__ float2 unpk(ull v) {
    float2 r; asm("mov.b64 {%0,%1}, %2;" : "=f"(r.x), "=f"(r.y) : "l"(v)); return r;
}
__device__ __forceinline__ void ffma2(ull &d, ull a, ull b) {
    asm("fma.rn.f32x2 %0, %1, %2, %0;" : "+l"(d) : "l"(a), "l"(b));
}

// ------------------------- prep: pair indices + g ---------------------------
__device__ __forceinline__ long long pair_off(long long i) {
    return i * (2LL*En - i - 1) / 2;
}

__global__ void pair_kernel(const float* __restrict__ v) {
    int p = blockIdx.x * 256 + threadIdx.x;
    if (p >= KPAD) return;
    if (p >= NPAIR) { d_pairs[p] = 0; return; }
    double a = 2.0*En - 1.0;
    int i = (int)((a - sqrt(a*a - 8.0*(double)p)) * 0.5);
    if (i < 0) i = 0; if (i > En-2) i = En-2;
    while (i > 0 && pair_off(i) > p) i--;
    while (i < En-2 && pair_off(i+1) <= p) i++;
    int j = i + 1 + (int)((long long)p - pair_off(i));
    d_pairs[p] = ((unsigned)i << 16) | (unsigned)j;
    float g = 0.f;
    #pragma unroll
    for (int c = 0; c < Cn; c++) g += v[i*Cn+c] * v[j*Cn+c];
    d_g[p] = g;
}

// transpose fc7_w [300, NPAIR] -> W7gT [KPAD, 320], scaled by g[p], zero pad
__global__ void w7g_kernel(const float* __restrict__ fc7_w) {
    __shared__ float tile[32][33];
    int p0 = blockIdx.x * 32, o0 = blockIdx.y * 32;
    int tx = threadIdx.x, ty = threadIdx.y;
    int o = o0 + ty, p = p0 + tx;
    tile[ty][tx] = (o < En && p < NPAIR) ? fc7_w[(size_t)o*NPAIR + p] : 0.f;
    __syncthreads();
    int pw = p0 + ty, ow = o0 + tx;
    float gv = (pw < NPAIR) ? d_g[pw] : 0.f;
    d_W7gT[(size_t)pw*NOP + ow] = tile[tx][ty] * gv;
}

// ------------------------- attention pass 1 ---------------------------------
__global__ void attn_kernel(const float* __restrict__ x,
                            const float* __restrict__ w1, const float* __restrict__ b1,
                            const float* __restrict__ q1,
                            const float* __restrict__ w3, const float* __restrict__ b3,
                            const float* __restrict__ q3) {
    __shared__ float ws[16*En];
    __shared__ float bs[16], qs[16];
    int tid = threadIdx.x;
    for (int idx = tid; idx < 16*En; idx += blockDim.x) {
        int t = idx / En, e = idx % En;
        ws[idx] = (t < 8) ? w1[t*En + e] : w3[(t-8)*En + e];
    }
    if (tid < 8)       { bs[tid] = b1[tid];   qs[tid] = q1[tid]; }
    else if (tid < 16) { bs[tid] = b3[tid-8]; qs[tid] = q3[tid-8]; }
    __syncthreads();

    int lane = tid & 31;
    int gw = blockIdx.x * (blockDim.x >> 5) + (tid >> 5);
    int nw = gridDim.x * (blockDim.x >> 5);
    for (int item = gw; item < Bn*Sn; item += nw) {
        const float* xp = x + (size_t)item * En;
        float dot[16];
        #pragma unroll
        for (int t = 0; t < 16; t++) dot[t] = 0.f;
        float ab = 0.f;
        for (int e = lane; e < En; e += 32) {
            float xv = xp[e];
            ab += fabsf(xv);
            #pragma unroll
            for (int t = 0; t < 16; t++) dot[t] += xv * ws[t*En + e];
        }
        #pragma unroll
        for (int o = 16; o > 0; o >>= 1) {
            ab += __shfl_down_sync(0xffffffffu, ab, o);
            #pragma unroll
            for (int t = 0; t < 16; t++) dot[t] += __shfl_down_sync(0xffffffffu, dot[t], o);
        }
        if (lane == 0) {
            #pragma unroll
            for (int h = 0; h < 2; h++) {
                float asum = 0.f, asq = 0.f, aq = 0.f;
                #pragma unroll
                for (int t = 0; t < 8; t++) {
                    float av = dot[h*8+t] + bs[h*8+t];
                    av = av > 0.f ? av : 0.f;
                    asum += av; asq += av*av; aq += av * qs[h*8+t];
                }
                d_Aq[h][item] = aq; d_Asm[h][item] = asum; d_Asq[h][item] = asq;
            }
            d_sgn[item] = ab;
        }
    }
}

// per-s BN stats over (b, t)  — deterministic reduction
__global__ void attn_stats_kernel(const float* __restrict__ q1,
                                  const float* __restrict__ q3) {
    int s = blockIdx.x, h = blockIdx.y;
    __shared__ float r1[256], r2[256];
    float a = 0.f, b = 0.f;
    for (int bb = threadIdx.x; bb < Bn; bb += 256) {
        a += d_Asm[h][bb*Sn + s];
        b += d_Asq[h][bb*Sn + s];
    }
    r1[threadIdx.x] = a; r2[threadIdx.x] = b; __syncthreads();
    for (int o = 128; o > 0; o >>= 1) {
        if (threadIdx.x < o) { r1[threadIdx.x] += r1[threadIdx.x+o]; r2[threadIdx.x] += r2[threadIdx.x+o]; }
        __syncthreads();
    }
    if (threadIdx.x == 0) {
        float n = (float)(Bn * Tn);
        float m = r1[0] / n;
        float var = r2[0] / n - m*m;
        d_m[h][s] = m;
        d_is[h][s] = rsqrtf(var + EPSf);
        if (s == 0) {
            const float* q = h ? q3 : q1;
            float Q = 0.f;
            for (int t = 0; t < 8; t++) Q += q[t];
            d_Q[h] = Q;
        }
    }
}

// ------------------------- softmax + pooling (pass 2 over x) ----------------
__global__ void pool_kernel(const float* __restrict__ x) {
    int b = blockIdx.x;
    __shared__ float w0[Sn], w1s[Sn];
    int tid = threadIdx.x;
    if (tid < Sn) {
        int item = b*Sn + tid;
        float sg = d_sgn[item];
        float s0 = (sg == 0.f) ? PADVAL : (d_Aq[0][item] - d_m[0][tid]*d_Q[0]) * d_is[0][tid];
        float s1 = (sg == 0.f) ? PADVAL : (d_Aq[1][item] - d_m[1][tid]*d_Q[1]) * d_is[1][tid];
        w0[tid] = s0; w1s[tid] = s1;
    }
    __syncthreads();
    float mx0 = -INFINITY, mx1 = -INFINITY;
    for (int s = 0; s < Sn; s++) { mx0 = fmaxf(mx0, w0[s]); mx1 = fmaxf(mx1, w1s[s]); }
    __syncthreads();
    if (tid < Sn) { w0[tid] = expf(w0[tid]-mx0); w1s[tid] = expf(w1s[tid]-mx1); }
    __syncthreads();
    float sm0 = 0.f, sm1 = 0.f;
    for (int s = 0; s < Sn; s++) { sm0 += w0[s]; sm1 += w1s[s]; }
    float inv0 = 1.f/sm0, inv1 = 1.f/sm1;
    if (tid < En) {
        float a0 = 0.f, a1 = 0.f;
        const float* xp = x + (size_t)b*Sn*En + tid;
        for (int s = 0; s < Sn; s++) {
            float xv = xp[(size_t)s*En];
            a0 += w0[s]*xv; a1 += w1s[s]*xv;
        }
        d_h[(size_t)b*600 + tid]       = a0*inv0;
        d_h[(size_t)b*600 + 300 + tid] = a1*inv1;
    }
}

// ------------------------- generic SGEMM  C[M,N] = A[M,K] @ W[N,K]^T (+bias) -
// BM=64 BN=64 BK=12, 256 threads, 4x4 micro-tile via f32x2 packed FMA
__global__ void gemm_kernel(const float* __restrict__ A, const float* __restrict__ W,
                            float* __restrict__ Cout, const float* __restrict__ bias,
                            int N, int K) {
    __shared__ float As[12*68];
    __shared__ float Ws[12*68];
    int m0 = blockIdx.y * 64, n0 = blockIdx.x * 64;
    int tid = threadIdx.x;
    int ty = tid >> 4, tx = tid & 15;
    ull acc[4][2];
    #pragma unroll
    for (int i = 0; i < 4; i++) { acc[i][0] = 0ULL; acc[i][1] = 0ULL; }

    for (int kc = 0; kc < K; kc += 12) {
        for (int idx = tid; idx < 64*12; idx += 256) {
            int r = idx / 12, kk = idx % 12;
            As[kk*68 + r] = A[(size_t)(m0+r)*K + kc + kk];
        }
        for (int idx = tid; idx < 64*12; idx += 256) {
            int c = idx / 12, kk = idx % 12;
            int col = n0 + c;
            Ws[kk*68 + c] = (col < N) ? W[(size_t)col*K + kc + kk] : 0.f;
        }
        __syncthreads();
        #pragma unroll
        for (int kk = 0; kk < 12; kk++) {
            float4 av = *(const float4*)&As[kk*68 + ty*4];
            float4 bv = *(const float4*)&Ws[kk*68 + tx*4];
            ull b01 = pack2(bv.x, bv.y), b23 = pack2(bv.z, bv.w);
            ull a;
            a = pack2(av.x, av.x); ffma2(acc[0][0], a, b01); ffma2(acc[0][1], a, b23);
            a = pack2(av.y, av.y); ffma2(acc[1][0], a, b01); ffma2(acc[1][1], a, b23);
            a = pack2(av.z, av.z); ffma2(acc[2][0], a, b01); ffma2(acc[2][1], a, b23);
            a = pack2(av.w, av.w); ffma2(acc[3][0], a, b01); ffma2(acc[3][1], a, b23);
        }
        __syncthreads();
    }
    #pragma unroll
    for (int i = 0; i < 4; i++) {
        int row = m0 + ty*4 + i;
        #pragma unroll
        for (int jj = 0; jj < 2; jj++) {
            float2 vv = unpk(acc[i][jj]);
            int col = n0 + tx*4 + jj*2;
            if (col < N)     Cout[(size_t)row*N + col]     = vv.x + (bias ? bias[col]   : 0.f);
            if (col + 1 < N) Cout[(size_t)row*N + col + 1] = vv.y + (bias ? bias[col+1] : 0.f);
        }
    }
}

// ------------------------- fc7 fused cross-GEMM -----------------------------
// C[b,o] += sum_p h5[b,i_p]*h5[b,j_p] * W7gT[p,o]; split-K over blockIdx.z
__global__ void fc7_kernel() {
    extern __shared__ float sm[];
    float* h5s = sm;                                // 64*301
    float* As  = sm + 64*301;                       // 32*68
    float* Bs  = As + 32*68;                        // 32*68
    unsigned int* pair_s = (unsigned int*)(Bs + 32*68); // 32

    int m0 = blockIdx.y * 64;
    int n0 = blockIdx.x * 64;
    int tid = threadIdx.x;
    int ty = tid >> 4, tx = tid & 15;

    for (int idx = tid; idx < 64*En; idx += 256) {
        int r = idx / En, e = idx % En;
        h5s[r*301 + e] = d_h5[(size_t)(m0+r)*En + e];
    }
    __syncthreads();

    ull acc[4][2];
    #pragma unroll
    for (int i = 0; i < 4; i++) { acc[i][0] = 0ULL; acc[i][1] = 0ULL; }

    const int per = (NCHUNK + KSPLIT - 1) / KSPLIT;     // 176
    int c0 = blockIdx.z * per;
    int c1 = c0 + per; if (c1 > NCHUNK) c1 = NCHUNK;

    for (int kc = c0; kc < c1; kc++) {
        int k0 = kc * 32;
        if (tid < 32) pair_s[tid] = d_pairs[k0 + tid];
        #pragma unroll
        for (int t = 0; t < 8; t++) {
            int idx = tid + t*256;
            int kk = idx >> 6, col = idx & 63;
            Bs[kk*68 + col] = d_W7gT[(size_t)(k0+kk)*NOP + n0 + col];
        }
        __syncthreads();
        #pragma unroll
        for (int t = 0; t < 8; t++) {
            int idx = tid + t*256;
            int row = idx & 63, kk = idx >> 6;
            unsigned int pp = pair_s[kk];
            int i = pp >> 16, j = pp & 0xFFFF;
            As[kk*68 + row] = h5s[row*301 + i] * h5s[row*301 + j];
        }
        __syncthreads();
        #pragma unroll
        for (int kk = 0; kk < 32; kk++) {
            float4 av = *(const float4*)&As[kk*68 + ty*4];
            float4 bv = *(const float4*)&Bs[kk*68 + tx*4];
            ull b01 = pack2(bv.x, bv.y), b23 = pack2(bv.z, bv.w);
            ull a;
            a = pack2(av.x, av.x); ffma2(acc[0][0], a, b01); ffma2(acc[0][1], a, b23);
            a = pack2(av.y, av.y); ffma2(acc[1][0], a, b01); ffma2(acc[1][1], a, b23);
            a = pack2(av.z, av.z); ffma2(acc[2][0], a, b01); ffma2(acc[2][1], a, b23);
            a = pack2(av.w, av.w); ffma2(acc[3][0], a, b01); ffma2(acc[3][1], a, b23);
        }
        __syncthreads();
    }
    #pragma unroll
    for (int i = 0; i < 4; i++) {
        int row = m0 + ty*4 + i;
        #pragma unroll
        for (int jj = 0; jj < 2; jj++) {
            float2 vv = unpk(acc[i][jj]);
            int col = n0 + tx*4 + jj*2;
            if (col < En)     atomicAdd(&d_h7p[(size_t)row*En + col],     vv.x);
            if (col + 1 < En) atomicAdd(&d_h7p[(size_t)row*En + col + 1], vv.y);
        }
    }
}

// ------------------------- BN helpers ---------------------------------------
__global__ void zero_kernel(float* __restrict__ p, int n) {
    int i = blockIdx.x*256 + threadIdx.x;
    if (i < n) p[i] = 0.f;
}

__global__ void colstats_kernel(const float* __restrict__ X, int N) {
    int c = blockIdx.x;
    __shared__ float r1[256], r2[256];
    float a = 0.f, b = 0.f;
    for (int r = threadIdx.x; r < Bn; r += 256) {
        float v = X[(size_t)r*N + c];
        a += v; b += v*v;
    }
    r1[threadIdx.x] = a; r2[threadIdx.x] = b; __syncthreads();
    for (int o = 128; o > 0; o >>= 1) {
        if (threadIdx.x < o) { r1[threadIdx.x] += r1[threadIdx.x+o]; r2[threadIdx.x] += r2[threadIdx.x+o]; }
        __syncthreads();
    }
    if (threadIdx.x == 0) {
        float m = r1[0] / (float)Bn;
        float var = r2[0] / (float)Bn - m*m;
        d_cm[c] = m;
        d_cis[c] = rsqrtf(var + EPSf);
    }
}

__global__ void normalize_kernel(const float* __restrict__ X, float* __restrict__ Y,
                                 int N, int ystride, int yoff) {
    int idx = blockIdx.x*256 + threadIdx.x;
    if (idx < Bn*N) {
        int r = idx / N, c = idx % N;
        Y[(size_t)r*ystride + yoff + c] = (X[idx] - d_cm[c]) * d_cis[c];
    }
}

// ------------------------- launch -------------------------------------------
extern "C" void kernel_launch(void* const* d_in, const int* in_sizes, int n_in,
                              void* d_out, int out_size) {
    const float* x      = (const float*)d_in[0];
    const float* lab    = (const float*)d_in[1];
    const float* fc1_w  = (const float*)d_in[2];
    const float* fc1_b  = (const float*)d_in[3];
    const float* q1     = (const float*)d_in[4];
    const float* fc3_w  = (const float*)d_in[5];
    const float* fc3_b  = (const float*)d_in[6];
    const float* q2     = (const float*)d_in[7];
    const float* fc5_w  = (const float*)d_in[8];
    const float* fc6_w  = (const float*)d_in[10];
    const float* fc7_w  = (const float*)d_in[12];
    const float* fc8_w  = (const float*)d_in[14];
    const float* fc8_b  = (const float*)d_in[15];
    const float* v      = (const float*)d_in[16];
    float* out = (float*)d_out;

    // device-global scratch addresses (host-visible pointers)
    float *ph, *ph5, *ph6p, *ph7p, *phcat, *pout8;
    cudaGetSymbolAddress((void**)&ph,    d_h);
    cudaGetSymbolAddress((void**)&ph5,   d_h5);
    cudaGetSymbolAddress((void**)&ph6p,  d_h6p);
    cudaGetSymbolAddress((void**)&ph7p,  d_h7p);
    cudaGetSymbolAddress((void**)&phcat, d_hcat);
    cudaGetSymbolAddress((void**)&pout8, d_out8);

    const int fc7_smem = (64*301 + 2*32*68) * 4 + 32*4;   // ~94.7 KB
    cudaFuncSetAttribute(fc7_kernel, cudaFuncAttributeMaxDynamicSharedMemorySize, fc7_smem);

    // prep: pairs + g, then W7gT = fc7_w^T * g (zero-padded)
    pair_kernel<<<(KPAD + 255)/256, 256>>>(v);
    w7g_kernel<<<dim3(KPAD/32, NOP/32), dim3(32, 32)>>>(fc7_w);

    // attention pooling
    attn_kernel<<<1184, 256>>>(x, fc1_w, fc1_b, q1, fc3_w, fc3_b, q2);
    attn_stats_kernel<<<dim3(Sn, 2), 256>>>(q1, q2);
    pool_kernel<<<Bn, 320>>>(x);

    // fc5 -> BN -> h5 (bias cancels under BN)
    gemm_kernel<<<dim3(5, Bn/64), 256>>>(ph, fc5_w, ph5, nullptr, En, 600);
    colstats_kernel<<<En, 256>>>(ph5, En);
    normalize_kernel<<<(Bn*En + 255)/256, 256>>>(ph5, ph5, En, En, 0);

    // fc6 (pre-BN) and fused cross-feature fc7 (pre-BN)
    gemm_kernel<<<dim3(5, Bn/64), 256>>>(ph5, fc6_w, ph6p, nullptr, En, En);
    zero_kernel<<<(Bn*En + 255)/256, 256>>>(ph7p, Bn*En);
    fc7_kernel<<<dim3(5, Bn/64, KSPLIT), 256, fc7_smem>>>();

    // BN both into the concat buffer
    colstats_kernel<<<En, 256>>>(ph6p, En);
    normalize_kernel<<<(Bn*En + 255)/256, 256>>>(ph6p, phcat, En, 600, 0);
    colstats_kernel<<<En, 256>>>(ph7p, En);
    normalize_kernel<<<(Bn*En + 255)/256, 256>>>(ph7p, phcat, En, 600, 300);

    // fc8 (+bias) and final label projection
    gemm_kernel<<<dim3(5, Bn/64), 256>>>(phcat, fc8_w, pout8, fc8_b, Un, 600);
    gemm_kernel<<<dim3(16, Bn/64), 256>>>(pout8, lab, out, nullptr, Ln, Un);
}